// round 14
// baseline (speedup 1.0000x reference)
#include <cuda_runtime.h>
#include <cstdint>

// RotateMyLayer: STN affine bilinear warp of ROIs from a batched feature map.
// feature_map: [8, 160, 160, 256] f32
// transform_matrixs: [10, 6] f32
// box_masks: [10] i32 (batch index per roi)
// box_widths: [10] i32
// out: [10, 8, 384, 256] f32

#define OUT_H   8
#define MAX_W   384
#define MAX_ROI 10
#define FH      160
#define FW      160
#define NC      256
#define NC4     (NC / 4)    // 64 float4 per pixel

// Packed fp32x2 helpers (Blackwell FFMA2 — only reachable via PTX).
__device__ __forceinline__ uint64_t pack2(float v) {
    uint64_t r;
    asm("mov.b64 %0, {%1, %1};" : "=l"(r) : "f"(v));
    return r;
}
__device__ __forceinline__ uint64_t fma2(uint64_t a, uint64_t b, uint64_t c) {
    uint64_t d;
    asm("fma.rn.f32x2 %0, %1, %2, %3;" : "=l"(d) : "l"(a), "l"(b), "l"(c));
    return d;
}
__device__ __forceinline__ uint64_t mul2(uint64_t a, uint64_t b) {
    uint64_t d;
    asm("mul.rn.f32x2 %0, %1, %2;" : "=l"(d) : "l"(a), "l"(b));
    return d;
}

// (128, 16): pins ptxas to <=32 regs so 16 CTAs (2048 threads) stay resident.
__global__ __launch_bounds__(128, 16) void stn_warp_kernel(
    const float* __restrict__ fm,
    const float* __restrict__ thetas,
    const int*   __restrict__ masks,
    const int*   __restrict__ widths,
    float*       __restrict__ out)
{
    // One warp per (roi, i, j) tuple; each lane handles 8 channels (2 float4).
    // grid = (96, 80), block = 128 (4 warps = 4 adjacent j -> L1 corner reuse).
    const int warp = threadIdx.x >> 5;
    const int lane = threadIdx.x & 31;
    const int j    = blockIdx.x * 4 + warp;   // 0..383
    const int t    = blockIdx.y;              // 0..79  (= roi*8 + i)
    const int i    = t & 7;
    const int roi  = t >> 3;

    // 32-bit offsets everywhere (fm = 26M float4, out = 2M float4).
    ulonglong2* op = reinterpret_cast<ulonglong2*>(out)
                   + (t * MAX_W + j) * NC4 + lane;

    const int w = __ldg(&widths[roi]);
    if (j >= w) {
        const ulonglong2 z = make_ulonglong2(0ull, 0ull);
        op[0]  = z;
        op[32] = z;
        return;
    }

    const float2* th = reinterpret_cast<const float2*>(thetas + roi * 6);
    const float2 th0 = __ldg(&th[0]);   // t00, t01
    const float2 th1 = __ldg(&th[1]);   // t02, t10
    const float2 th2 = __ldg(&th[2]);   // t11, t12
    const int    b   = __ldg(&masks[roi]);

    const float denom = (float)((w - 1) > 1 ? (w - 1) : 1);
    const float x_t = -1.0f + 2.0f * __fdividef((float)j, denom);
    const float y_t = -1.0f + 2.0f * (float)i * (1.0f / 7.0f);

    const float xs = th0.x * x_t + th0.y * y_t + th1.x;
    const float ys = th1.y * x_t + th2.x * y_t + th2.y;
    const float x  = (xs + 1.0f) * (0.5f * (float)FW);
    const float y  = (ys + 1.0f) * (0.5f * (float)FH);

    const float x0f = floorf(x);
    const float y0f = floorf(y);
    const int x0 = min(max((int)x0f,     0), FW - 1);
    const int x1 = min(max((int)x0f + 1, 0), FW - 1);
    const int y0 = min(max((int)y0f,     0), FH - 1);
    const int y1 = min(max((int)y0f + 1, 0), FH - 1);

    // Addresses first -> issue LDG.128s ASAP.
    const ulonglong2* pa = reinterpret_cast<const ulonglong2*>(fm)
        + (b * (FH * FW) + y0 * FW + x0) * NC4 + lane;
    const int dRow = (y1 - y0) * (FW * NC4);   // 0 or FW*NC4
    const int dCol = (x1 - x0) * NC4;          // 0 or NC4

    const ulonglong2 Ia0 = pa[0];
    const ulonglong2 Ia1 = pa[32];
    const ulonglong2 Ib0 = pa[dRow];
    const ulonglong2 Ib1 = pa[dRow + 32];
    const ulonglong2 Ic0 = pa[dCol];
    const ulonglong2 Ic1 = pa[dCol + 32];
    const ulonglong2 Id0 = pa[dRow + dCol];
    const ulonglong2 Id1 = pa[dRow + dCol + 32];

    // Weight math lives in the load shadow; weights broadcast-packed f32x2.
    const float dx = x - x0f;
    const float dy = y - y0f;
    const uint64_t wa = pack2((1.0f - dx) * (1.0f - dy));
    const uint64_t wb = pack2((1.0f - dx) * dy);
    const uint64_t wc = pack2(dx * (1.0f - dy));
    const uint64_t wd = pack2(dx * dy);

    // Blend: 16 FFMA2/FMUL2 instead of 32 scalar FFMA.
    ulonglong2 r0, r1;
    r0.x = fma2(wa, Ia0.x, fma2(wb, Ib0.x, fma2(wc, Ic0.x, mul2(wd, Id0.x))));
    r0.y = fma2(wa, Ia0.y, fma2(wb, Ib0.y, fma2(wc, Ic0.y, mul2(wd, Id0.y))));
    r1.x = fma2(wa, Ia1.x, fma2(wb, Ib1.x, fma2(wc, Ic1.x, mul2(wd, Id1.x))));
    r1.y = fma2(wa, Ia1.y, fma2(wb, Ib1.y, fma2(wc, Ic1.y, mul2(wd, Id1.y))));

    op[0]  = r0;
    op[32] = r1;
}

extern "C" void kernel_launch(void* const* d_in, const int* in_sizes, int n_in,
                              void* d_out, int out_size)
{
    const float* fm     = (const float*)d_in[0];
    const float* thetas = (const float*)d_in[1];
    const int*   masks  = (const int*)d_in[2];
    const int*   widths = (const int*)d_in[3];
    float*       out    = (float*)d_out;

    dim3 grid(MAX_W / 4, MAX_ROI * OUT_H);   // (96, 80)
    stn_warp_kernel<<<grid, 128>>>(fm, thetas, masks, widths, out);
}